// round 2
// baseline (speedup 1.0000x reference)
#include <cuda_runtime.h>
#include <math.h>

// Problem constants (from reference): N=50000, E=800000, D_IN=256, D_OUT=128, H=16
#define NMAX   50000
#define DOUT   128
#define DIN    256
#define HEDGE  16

// Scratch (device globals: allocation-free per harness rules)
__device__ float g_xp[NMAX * DOUT];   // x_proj, 25.6 MB (L2-resident)
__device__ float g_s[NMAX];           // per-node gate: softplus(4*(sigmoid(mlp)-0.5))
__device__ float g_deg[NMAX];         // sum |w| per dst

// ---------------------------------------------------------------------------
// K0: zero accumulators (d_out is poisoned by harness)
// ---------------------------------------------------------------------------
__global__ void zero_kernel(float* __restrict__ out, int total_out, int n) {
    int i = blockIdx.x * blockDim.x + threadIdx.x;
    int stride = gridDim.x * blockDim.x;
    for (int j = i; j < total_out; j += stride) out[j] = 0.0f;
    for (int j = i; j < n; j += stride) g_deg[j] = 0.0f;
}

// ---------------------------------------------------------------------------
// K1: x_proj = concat(x,state) @ W_in + b_in
// Tile: 32 nodes x 128 cols per CTA (256 threads), 4x4 register micro-tile.
// ---------------------------------------------------------------------------
__global__ void proj_kernel(const float* __restrict__ x,
                            const float* __restrict__ state,
                            const float* __restrict__ Win,
                            const float* __restrict__ bin,
                            int n) {
    __shared__ float sx[32][DIN];   // 32 KB
    const int n0  = blockIdx.x * 32;
    const int tid = threadIdx.x;

    // cooperative load of the 32 x 256 input tile (concat on the fly)
    for (int idx = tid; idx < 32 * DIN; idx += 256) {
        int node = idx >> 8;          // /256
        int k    = idx & 255;
        int gn   = n0 + node;
        float v  = 0.0f;
        if (gn < n) v = (k < 128) ? x[(size_t)gn * 128 + k]
                                  : state[(size_t)gn * 128 + (k - 128)];
        sx[node][k] = v;
    }
    __syncthreads();

    const int q    = tid >> 5;        // node quad 0..7 -> nodes 4q..4q+3
    const int lane = tid & 31;
    const int c0   = lane * 4;        // 4 contiguous output cols

    float acc[4][4];
#pragma unroll
    for (int i = 0; i < 4; i++)
#pragma unroll
        for (int j = 0; j < 4; j++) acc[i][j] = 0.0f;

#pragma unroll 4
    for (int k = 0; k < DIN; k++) {
        float4 w4 = *(const float4*)(Win + (size_t)k * 128 + c0);
#pragma unroll
        for (int i = 0; i < 4; i++) {
            float xv = sx[q * 4 + i][k];
            acc[i][0] += xv * w4.x;
            acc[i][1] += xv * w4.y;
            acc[i][2] += xv * w4.z;
            acc[i][3] += xv * w4.w;
        }
    }

    float4 bv = *(const float4*)(bin + c0);
#pragma unroll
    for (int i = 0; i < 4; i++) {
        int gn = n0 + q * 4 + i;
        if (gn < n) {
            float4 o;
            o.x = acc[i][0] + bv.x;
            o.y = acc[i][1] + bv.y;
            o.z = acc[i][2] + bv.z;
            o.w = acc[i][3] + bv.w;
            *(float4*)(g_xp + (size_t)gn * 128 + c0) = o;
        }
    }
}

// ---------------------------------------------------------------------------
// K2: per-node gate (the edge MLP depends only on src -> hoist to nodes)
// s[n] = softplus(4*(sigmoid(leaky(xp@W1+b1)@W2+b2) - 0.5))
// ---------------------------------------------------------------------------
__global__ void gate_kernel(const float* __restrict__ W1,
                            const float* __restrict__ b1,
                            const float* __restrict__ W2,
                            const float* __restrict__ b2,
                            int n) {
    __shared__ float sW1[DOUT * HEDGE];   // 8 KB
    __shared__ float sW2[HEDGE];
    __shared__ float sb1[HEDGE];
    for (int i = threadIdx.x; i < DOUT * HEDGE; i += blockDim.x) sW1[i] = W1[i];
    if (threadIdx.x < HEDGE) {
        sW2[threadIdx.x] = W2[threadIdx.x];
        sb1[threadIdx.x] = b1[threadIdx.x];
    }
    __syncthreads();

    int nid = blockIdx.x * blockDim.x + threadIdx.x;
    if (nid >= n) return;

    float h[HEDGE];
#pragma unroll
    for (int j = 0; j < HEDGE; j++) h[j] = sb1[j];

    const float* xp = g_xp + (size_t)nid * 128;
    for (int k = 0; k < 128; k += 4) {
        float4 xv4 = *(const float4*)(xp + k);
        float xs[4] = {xv4.x, xv4.y, xv4.z, xv4.w};
#pragma unroll
        for (int kk = 0; kk < 4; kk++) {
#pragma unroll
            for (int j = 0; j < HEDGE; j++)
                h[j] += xs[kk] * sW1[(k + kk) * HEDGE + j];
        }
    }

    float z = b2[0];
#pragma unroll
    for (int j = 0; j < HEDGE; j++) {
        float hv = h[j] > 0.0f ? h[j] : 0.1f * h[j];   // leaky_relu(0.1)
        z += hv * sW2[j];
    }
    float wd = 1.0f / (1.0f + expf(-z));               // sigmoid
    float zz = 4.0f * (wd - 0.5f);                     // in (-2, 2)
    g_s[nid] = log1pf(expf(zz));                       // softplus, no overflow risk
}

// ---------------------------------------------------------------------------
// K3: edge scatter. One warp per edge; lane l handles cols [4l, 4l+4).
// edge_index delivered by the harness as int32 (harness dtype set is
// {float32, int32, bf16}): src = ei[e], dst = ei[E + e].
// Unsigned bounds guard: skips garbage edges instead of crashing if the
// dtype assumption is ever wrong (gives a rel_err signal, not an IMA).
// ---------------------------------------------------------------------------
__global__ void edge_kernel(const int* __restrict__ ei,
                            const float* __restrict__ ew,
                            float* __restrict__ out,
                            int E, int n) {
    int wid  = (blockIdx.x * blockDim.x + threadIdx.x) >> 5;
    int lane = threadIdx.x & 31;
    if (wid >= E) return;

    int src = ei[wid];
    int dst = ei[(size_t)E + wid];
    if ((unsigned)src >= (unsigned)n || (unsigned)dst >= (unsigned)n) return;

    float w = ew[wid] * g_s[src];
    w = fminf(fmaxf(w, 0.0f), 5.0f);                   // clip to [0, EW_MAX]

    float4 v = *(const float4*)(g_xp + (size_t)src * 128 + lane * 4);
    float* o = out + (size_t)dst * 128 + lane * 4;
    atomicAdd(o + 0, w * v.x);
    atomicAdd(o + 1, w * v.y);
    atomicAdd(o + 2, w * v.z);
    atomicAdd(o + 3, w * v.w);
    if (lane == 0) atomicAdd(&g_deg[dst], fabsf(w));
}

// ---------------------------------------------------------------------------
// K4: finalize: gelu(out/(deg+eps) + x_proj)  (exact gelu via erf)
// ---------------------------------------------------------------------------
__global__ void finalize_kernel(float* __restrict__ out, int n) {
    int i = blockIdx.x * blockDim.x + threadIdx.x;
    int total = n * 128;
    if (i >= total) return;
    int nid = i >> 7;
    float v = out[i] / (g_deg[nid] + 1e-6f) + g_xp[i];
    out[i] = 0.5f * v * (1.0f + erff(v * 0.70710678118654752f));
}

// ---------------------------------------------------------------------------
extern "C" void kernel_launch(void* const* d_in, const int* in_sizes, int n_in,
                              void* d_out, int out_size) {
    const float* x     = (const float*)d_in[0];
    const float* state = (const float*)d_in[1];
    const int*   ei    = (const int*)d_in[2];
    const float* ew    = (const float*)d_in[3];
    const float* Win   = (const float*)d_in[4];
    const float* bin   = (const float*)d_in[5];
    const float* W1    = (const float*)d_in[6];
    const float* b1    = (const float*)d_in[7];
    const float* W2    = (const float*)d_in[8];
    const float* b2    = (const float*)d_in[9];

    int n = in_sizes[0] / 128;     // 50000
    int E = in_sizes[3];           // 800000
    float* out = (float*)d_out;

    zero_kernel<<<512, 256>>>(out, out_size, n);
    proj_kernel<<<(n + 31) / 32, 256>>>(x, state, Win, bin, n);
    gate_kernel<<<(n + 255) / 256, 256>>>(W1, b1, W2, b2, n);

    // one warp per edge
    int edge_blocks = (int)(((long long)E * 32 + 255) / 256);
    edge_kernel<<<edge_blocks, 256>>>(ei, ew, out, E, n);

    finalize_kernel<<<(n * 128 + 255) / 256, 256>>>(out, n);
}

// round 3
// speedup vs baseline: 1.4732x; 1.4732x over previous
#include <cuda_runtime.h>
#include <math.h>

// Problem constants: N=50000, E=800000, D_IN=256, D_OUT=128, H=16
#define NMAX   50000
#define DOUT   128
#define DIN    256
#define HEDGE  16

// Scratch (device globals: allocation-free per harness rules)
__device__ float g_xp[NMAX * DOUT];   // x_proj, 25.6 MB (L2-resident)
__device__ float g_s[NMAX];           // per-node gate
__device__ float g_deg[NMAX];         // sum |w| per dst

// ---------------------------------------------------------------------------
// K0: zero accumulators (d_out is poisoned by harness), float4 stores
// ---------------------------------------------------------------------------
__global__ void zero_kernel(float4* __restrict__ out4, int total4, int n) {
    int i = blockIdx.x * blockDim.x + threadIdx.x;
    int stride = gridDim.x * blockDim.x;
    float4 z = make_float4(0.f, 0.f, 0.f, 0.f);
    for (int j = i; j < total4; j += stride) out4[j] = z;
    for (int j = i; j < n; j += stride) g_deg[j] = 0.0f;
}

// ---------------------------------------------------------------------------
// K1: x_proj = concat(x,state) @ W_in + b_in
// 32 nodes x 128 cols per CTA (256 threads), 4x4 micro-tile computed as
// 4x2 packed f32x2 (Blackwell FFMA2) — halves fma-pipe pressure.
// ---------------------------------------------------------------------------
__global__ void proj_kernel(const float* __restrict__ x,
                            const float* __restrict__ state,
                            const float* __restrict__ Win,
                            const float* __restrict__ bin,
                            int n) {
    __shared__ float sx[32][DIN];   // 32 KB
    const int n0  = blockIdx.x * 32;
    const int tid = threadIdx.x;

    for (int idx = tid; idx < 32 * DIN; idx += 256) {
        int node = idx >> 8;
        int k    = idx & 255;
        int gn   = n0 + node;
        float v  = 0.0f;
        if (gn < n) v = (k < 128) ? x[(size_t)gn * 128 + k]
                                  : state[(size_t)gn * 128 + (k - 128)];
        sx[node][k] = v;
    }
    __syncthreads();

    const int q    = tid >> 5;        // 8 warps -> node quads
    const int lane = tid & 31;
    const int c0   = lane * 4;

    // acc2[i][0] = cols (c0, c0+1), acc2[i][1] = cols (c0+2, c0+3), packed f32x2
    unsigned long long acc2[4][2];
#pragma unroll
    for (int i = 0; i < 4; i++) {
        acc2[i][0] = 0ull;
        acc2[i][1] = 0ull;
    }

#pragma unroll 4
    for (int k = 0; k < DIN; k++) {
        float4 w4 = *(const float4*)(Win + (size_t)k * 128 + c0);
        unsigned long long wlo, whi;
        asm("mov.b64 %0, {%1, %2};" : "=l"(wlo) : "f"(w4.x), "f"(w4.y));
        asm("mov.b64 %0, {%1, %2};" : "=l"(whi) : "f"(w4.z), "f"(w4.w));
#pragma unroll
        for (int i = 0; i < 4; i++) {
            float xv = sx[q * 4 + i][k];
            unsigned long long xx;
            asm("mov.b64 %0, {%1, %1};" : "=l"(xx) : "f"(xv));
            asm("fma.rn.f32x2 %0, %1, %2, %0;" : "+l"(acc2[i][0]) : "l"(xx), "l"(wlo));
            asm("fma.rn.f32x2 %0, %1, %2, %0;" : "+l"(acc2[i][1]) : "l"(xx), "l"(whi));
        }
    }

    float4 bv = *(const float4*)(bin + c0);
#pragma unroll
    for (int i = 0; i < 4; i++) {
        int gn = n0 + q * 4 + i;
        if (gn < n) {
            float a0, a1, a2, a3;
            asm("mov.b64 {%0, %1}, %2;" : "=f"(a0), "=f"(a1) : "l"(acc2[i][0]));
            asm("mov.b64 {%0, %1}, %2;" : "=f"(a2), "=f"(a3) : "l"(acc2[i][1]));
            float4 o;
            o.x = a0 + bv.x;
            o.y = a1 + bv.y;
            o.z = a2 + bv.z;
            o.w = a3 + bv.w;
            *(float4*)(g_xp + (size_t)gn * 128 + c0) = o;
        }
    }
}

// ---------------------------------------------------------------------------
// K2: per-node gate (edge MLP depends only on src -> hoisted to nodes)
// ---------------------------------------------------------------------------
__global__ void gate_kernel(const float* __restrict__ W1,
                            const float* __restrict__ b1,
                            const float* __restrict__ W2,
                            const float* __restrict__ b2,
                            int n) {
    __shared__ float sW1[DOUT * HEDGE];   // 8 KB
    __shared__ float sW2[HEDGE];
    __shared__ float sb1[HEDGE];
    for (int i = threadIdx.x; i < DOUT * HEDGE; i += blockDim.x) sW1[i] = W1[i];
    if (threadIdx.x < HEDGE) {
        sW2[threadIdx.x] = W2[threadIdx.x];
        sb1[threadIdx.x] = b1[threadIdx.x];
    }
    __syncthreads();

    int nid = blockIdx.x * blockDim.x + threadIdx.x;
    if (nid >= n) return;

    float h[HEDGE];
#pragma unroll
    for (int j = 0; j < HEDGE; j++) h[j] = sb1[j];

    const float* xp = g_xp + (size_t)nid * 128;
    for (int k = 0; k < 128; k += 4) {
        float4 xv4 = *(const float4*)(xp + k);
        float xs[4] = {xv4.x, xv4.y, xv4.z, xv4.w};
#pragma unroll
        for (int kk = 0; kk < 4; kk++) {
#pragma unroll
            for (int j = 0; j < HEDGE; j++)
                h[j] += xs[kk] * sW1[(k + kk) * HEDGE + j];
        }
    }

    float z = b2[0];
#pragma unroll
    for (int j = 0; j < HEDGE; j++) {
        float hv = h[j] > 0.0f ? h[j] : 0.1f * h[j];   // leaky_relu(0.1)
        z += hv * sW2[j];
    }
    float wd = 1.0f / (1.0f + expf(-z));               // sigmoid
    float zz = 4.0f * (wd - 0.5f);                     // in (-2, 2)
    g_s[nid] = log1pf(expf(zz));                       // softplus
}

// ---------------------------------------------------------------------------
// K3: edge scatter. One warp per edge; lane l handles cols [4l, 4l+4).
// Vectorized L2 reduction: red.global.add.v4.f32 (sm_90+), 1 op per lane
// instead of 4 scalar atomics -> 4x fewer L2 reduction ops.
// ---------------------------------------------------------------------------
__global__ void edge_kernel(const int* __restrict__ ei,
                            const float* __restrict__ ew,
                            float* __restrict__ out,
                            int E, int n) {
    int wid  = (blockIdx.x * blockDim.x + threadIdx.x) >> 5;
    int lane = threadIdx.x & 31;
    if (wid >= E) return;

    int src = ei[wid];
    int dst = ei[(size_t)E + wid];
    if ((unsigned)src >= (unsigned)n || (unsigned)dst >= (unsigned)n) return;

    float w = ew[wid] * g_s[src];
    w = fminf(fmaxf(w, 0.0f), 5.0f);                   // clip to [0, EW_MAX]

    float4 v = *(const float4*)(g_xp + (size_t)src * 128 + lane * 4);
    float* o = out + (size_t)dst * 128 + lane * 4;
    asm volatile("red.global.add.v4.f32 [%0], {%1, %2, %3, %4};"
                 :: "l"(o), "f"(w * v.x), "f"(w * v.y), "f"(w * v.z), "f"(w * v.w)
                 : "memory");
    if (lane == 0) atomicAdd(&g_deg[dst], fabsf(w));
}

// ---------------------------------------------------------------------------
// K4: finalize: gelu(out/(deg+eps) + x_proj), float4-vectorized
// ---------------------------------------------------------------------------
__global__ void finalize_kernel(float4* __restrict__ out4, int n) {
    int i = blockIdx.x * blockDim.x + threadIdx.x;
    int total4 = n * 32;                 // 128 cols / 4
    if (i >= total4) return;
    int nid = i >> 5;
    float inv = 1.0f / (g_deg[nid] + 1e-6f);
    float4 a = out4[i];
    float4 p = ((const float4*)g_xp)[i];
    float v0 = a.x * inv + p.x;
    float v1 = a.y * inv + p.y;
    float v2 = a.z * inv + p.z;
    float v3 = a.w * inv + p.w;
    const float is2 = 0.70710678118654752f;
    float4 r;
    r.x = 0.5f * v0 * (1.0f + erff(v0 * is2));
    r.y = 0.5f * v1 * (1.0f + erff(v1 * is2));
    r.z = 0.5f * v2 * (1.0f + erff(v2 * is2));
    r.w = 0.5f * v3 * (1.0f + erff(v3 * is2));
    out4[i] = r;
}

// ---------------------------------------------------------------------------
extern "C" void kernel_launch(void* const* d_in, const int* in_sizes, int n_in,
                              void* d_out, int out_size) {
    const float* x     = (const float*)d_in[0];
    const float* state = (const float*)d_in[1];
    const int*   ei    = (const int*)d_in[2];
    const float* ew    = (const float*)d_in[3];
    const float* Win   = (const float*)d_in[4];
    const float* bin   = (const float*)d_in[5];
    const float* W1    = (const float*)d_in[6];
    const float* b1    = (const float*)d_in[7];
    const float* W2    = (const float*)d_in[8];
    const float* b2    = (const float*)d_in[9];

    int n = in_sizes[0] / 128;     // 50000
    int E = in_sizes[3];           // 800000
    float* out = (float*)d_out;

    zero_kernel<<<1024, 256>>>((float4*)out, out_size / 4, n);
    proj_kernel<<<(n + 31) / 32, 256>>>(x, state, Win, bin, n);
    gate_kernel<<<(n + 255) / 256, 256>>>(W1, b1, W2, b2, n);

    int edge_blocks = (int)(((long long)E * 32 + 255) / 256);
    edge_kernel<<<edge_blocks, 256>>>(ei, ew, out, E, n);

    finalize_kernel<<<(n * 32 + 255) / 256, 256>>>((float4*)out, n);
}

// round 4
// speedup vs baseline: 1.6216x; 1.1008x over previous
#include <cuda_runtime.h>
#include <cuda_bf16.h>
#include <math.h>

// Problem constants: N=50000, E=800000, D_IN=256, D_OUT=128, H=16
#define NMAX   50000
#define DOUT   128
#define DIN    256
#define HEDGE  16

#define MTILE  64      // nodes per CTA in proj_mma
#define P_A    264     // sA pitch in fp32 (1056 B rows)
#define P_B    24      // sB pitch in bf16 (48 B rows)

// Scratch (device globals: allocation-free per harness rules)
__device__ float g_xp[NMAX * DOUT];            // x_proj, 25.6 MB (L2-resident)
__device__ float g_s[NMAX];                    // per-node gate
__device__ float g_deg[NMAX];                  // sum |w| per dst
__device__ __nv_bfloat16 g_Wt_hi[DOUT * DIN];  // W_in^T hi plane [n][k]
__device__ __nv_bfloat16 g_Wt_lo[DOUT * DIN];  // W_in^T lo plane [n][k]

// ---------------------------------------------------------------------------
// helpers: bf16x2 split + bf16 mma
// ---------------------------------------------------------------------------
__device__ __forceinline__ void split2(float f0, float f1, unsigned& hi, unsigned& lo) {
    asm("cvt.rn.bf16x2.f32 %0, %1, %2;" : "=r"(hi) : "f"(f1), "f"(f0));   // lo half = f0
    float h0 = __uint_as_float(hi << 16);
    float h1 = __uint_as_float(hi & 0xffff0000u);
    float r0 = f0 - h0;                   // exact (Sterbenz)
    float r1 = f1 - h1;
    asm("cvt.rn.bf16x2.f32 %0, %1, %2;" : "=r"(lo) : "f"(r1), "f"(r0));
}

__device__ __forceinline__ void mma_bf16(float c[4], const unsigned a[4],
                                         unsigned b0, unsigned b1) {
    asm("mma.sync.aligned.m16n8k16.row.col.f32.bf16.bf16.f32 "
        "{%0,%1,%2,%3}, {%4,%5,%6,%7}, {%8,%9}, {%0,%1,%2,%3};"
        : "+f"(c[0]), "+f"(c[1]), "+f"(c[2]), "+f"(c[3])
        : "r"(a[0]), "r"(a[1]), "r"(a[2]), "r"(a[3]), "r"(b0), "r"(b1));
}

// ---------------------------------------------------------------------------
// K0: zero accumulators (d_out is poisoned by harness)
// ---------------------------------------------------------------------------
__global__ void zero_kernel(float4* __restrict__ out4, int total4, int n) {
    int i = blockIdx.x * blockDim.x + threadIdx.x;
    int stride = gridDim.x * blockDim.x;
    float4 z = make_float4(0.f, 0.f, 0.f, 0.f);
    for (int j = i; j < total4; j += stride) out4[j] = z;
    for (int j = i; j < n; j += stride) g_deg[j] = 0.0f;
}

// ---------------------------------------------------------------------------
// K0b: split + transpose W_in into bf16 hi/lo planes (one-time, ~2us)
// Win[k][n] (256x128) -> g_Wt_{hi,lo}[n][k]
// ---------------------------------------------------------------------------
__global__ void prepW_kernel(const float* __restrict__ Win) {
    int i = blockIdx.x * blockDim.x + threadIdx.x;
    if (i >= DIN * DOUT) return;
    int k  = i >> 7;
    int nn = i & 127;
    float w = Win[i];
    __nv_bfloat16 h = __float2bfloat16_rn(w);
    float hf = __bfloat162float(h);
    __nv_bfloat16 l = __float2bfloat16_rn(w - hf);
    g_Wt_hi[nn * DIN + k] = h;
    g_Wt_lo[nn * DIN + k] = l;
}

// ---------------------------------------------------------------------------
// K1: x_proj = concat(x,state) @ W_in + b_in via bf16 tensor cores,
// 3-term split (Ahi*Bhi + Ahi*Blo + Alo*Bhi) -> ~1e-6 accuracy.
// CTA: 64 nodes x 128 cols, 128 threads = 4 warps, warp tile 16x128.
// ---------------------------------------------------------------------------
__global__ void proj_mma_kernel(const float* __restrict__ x,
                                const float* __restrict__ state,
                                const float* __restrict__ bin,
                                int n) {
    extern __shared__ char smem[];
    float* sA = (float*)smem;                                    // [64][P_A] fp32
    __nv_bfloat16* sBhi = (__nv_bfloat16*)(smem + MTILE * P_A * 4);
    __nv_bfloat16* sBlo = sBhi + 128 * P_B;

    const int tid  = threadIdx.x;
    const int warp = tid >> 5;
    const int lane = tid & 31;
    const int gID  = lane >> 2;
    const int tID  = lane & 3;
    const int nb   = blockIdx.x * MTILE;

    // stage A tile (fp32, concat(x,state)) — coalesced float4
    for (int idx = tid; idx < MTILE * 64; idx += 128) {
        int node = idx >> 6;
        int kq   = idx & 63;
        int gn   = nb + node;
        float4 v = make_float4(0.f, 0.f, 0.f, 0.f);
        if (gn < n) v = (kq < 32) ? ((const float4*)x)[(size_t)gn * 32 + kq]
                                  : ((const float4*)state)[(size_t)gn * 32 + (kq - 32)];
        *(float4*)(sA + node * P_A + kq * 4) = v;
    }

    float c[16][4];
#pragma unroll
    for (int nt = 0; nt < 16; nt++)
#pragma unroll
        for (int j = 0; j < 4; j++) c[nt][j] = 0.0f;

    const int m0 = warp * 16;

    for (int kc = 0; kc < 16; kc++) {
        __syncthreads();   // (also covers initial A staging on kc==0)
        // stage B chunk: 128 n-rows x 16 k, hi & lo planes. thread t -> row t.
        {
            const uint4* sh = (const uint4*)(g_Wt_hi + tid * DIN + kc * 16);
            const uint4* sl = (const uint4*)(g_Wt_lo + tid * DIN + kc * 16);
            uint4 h0 = sh[0], h1 = sh[1];
            uint4 l0 = sl[0], l1 = sl[1];
            *(uint4*)(sBhi + tid * P_B)     = h0;
            *(uint4*)(sBhi + tid * P_B + 8) = h1;
            *(uint4*)(sBlo + tid * P_B)     = l0;
            *(uint4*)(sBlo + tid * P_B + 8) = l1;
        }
        __syncthreads();

        // A fragments for this k-chunk (split fp32 -> bf16 hi/lo on the fly)
        unsigned ah[4], al[4];
        const float* ar0 = sA + (m0 + gID) * P_A + kc * 16;
        const float* ar1 = sA + (m0 + gID + 8) * P_A + kc * 16;
        float2 p;
        p = *(const float2*)(ar0 + tID * 2);     split2(p.x, p.y, ah[0], al[0]);
        p = *(const float2*)(ar1 + tID * 2);     split2(p.x, p.y, ah[1], al[1]);
        p = *(const float2*)(ar0 + tID * 2 + 8); split2(p.x, p.y, ah[2], al[2]);
        p = *(const float2*)(ar1 + tID * 2 + 8); split2(p.x, p.y, ah[3], al[3]);

#pragma unroll
        for (int nt = 0; nt < 16; nt++) {
            const __nv_bfloat16* bh = sBhi + (nt * 8 + gID) * P_B + tID * 2;
            const __nv_bfloat16* bl = sBlo + (nt * 8 + gID) * P_B + tID * 2;
            unsigned bh0 = *(const unsigned*)(bh);
            unsigned bh1 = *(const unsigned*)(bh + 8);
            unsigned bl0 = *(const unsigned*)(bl);
            unsigned bl1 = *(const unsigned*)(bl + 8);
            mma_bf16(c[nt], ah, bh0, bh1);
            mma_bf16(c[nt], ah, bl0, bl1);
            mma_bf16(c[nt], al, bh0, bh1);
        }
    }

    // epilogue: + bias, store to g_xp
    int r0 = nb + m0 + gID;
    int r1 = r0 + 8;
#pragma unroll
    for (int nt = 0; nt < 16; nt++) {
        int col = nt * 8 + tID * 2;
        float2 bv = *(const float2*)(bin + col);
        if (r0 < n) {
            float2 o = make_float2(c[nt][0] + bv.x, c[nt][1] + bv.y);
            *(float2*)(g_xp + (size_t)r0 * 128 + col) = o;
        }
        if (r1 < n) {
            float2 o = make_float2(c[nt][2] + bv.x, c[nt][3] + bv.y);
            *(float2*)(g_xp + (size_t)r1 * 128 + col) = o;
        }
    }
}

// ---------------------------------------------------------------------------
// K2: per-node gate (edge MLP depends only on src -> hoisted to nodes)
// ---------------------------------------------------------------------------
__global__ void gate_kernel(const float* __restrict__ W1,
                            const float* __restrict__ b1,
                            const float* __restrict__ W2,
                            const float* __restrict__ b2,
                            int n) {
    __shared__ float sW1[DOUT * HEDGE];   // 8 KB
    __shared__ float sW2[HEDGE];
    __shared__ float sb1[HEDGE];
    for (int i = threadIdx.x; i < DOUT * HEDGE; i += blockDim.x) sW1[i] = W1[i];
    if (threadIdx.x < HEDGE) {
        sW2[threadIdx.x] = W2[threadIdx.x];
        sb1[threadIdx.x] = b1[threadIdx.x];
    }
    __syncthreads();

    int nid = blockIdx.x * blockDim.x + threadIdx.x;
    if (nid >= n) return;

    float h[HEDGE];
#pragma unroll
    for (int j = 0; j < HEDGE; j++) h[j] = sb1[j];

    const float* xp = g_xp + (size_t)nid * 128;
    for (int k = 0; k < 128; k += 4) {
        float4 xv4 = *(const float4*)(xp + k);
        float xs[4] = {xv4.x, xv4.y, xv4.z, xv4.w};
#pragma unroll
        for (int kk = 0; kk < 4; kk++) {
#pragma unroll
            for (int j = 0; j < HEDGE; j++)
                h[j] += xs[kk] * sW1[(k + kk) * HEDGE + j];
        }
    }

    float z = b2[0];
#pragma unroll
    for (int j = 0; j < HEDGE; j++) {
        float hv = h[j] > 0.0f ? h[j] : 0.1f * h[j];   // leaky_relu(0.1)
        z += hv * sW2[j];
    }
    float wd = 1.0f / (1.0f + expf(-z));               // sigmoid
    float zz = 4.0f * (wd - 0.5f);                     // in (-2, 2)
    g_s[nid] = log1pf(expf(zz));                       // softplus
}

// ---------------------------------------------------------------------------
// K3: edge scatter. One warp per edge; lane l handles cols [4l, 4l+4).
// red.global.add.v4.f32: 1 L2 reduction op per lane.
// ---------------------------------------------------------------------------
__global__ void edge_kernel(const int* __restrict__ ei,
                            const float* __restrict__ ew,
                            float* __restrict__ out,
                            int E, int n) {
    int wid  = (blockIdx.x * blockDim.x + threadIdx.x) >> 5;
    int lane = threadIdx.x & 31;
    if (wid >= E) return;

    int src = ei[wid];
    int dst = ei[(size_t)E + wid];
    if ((unsigned)src >= (unsigned)n || (unsigned)dst >= (unsigned)n) return;

    float w = ew[wid] * g_s[src];
    w = fminf(fmaxf(w, 0.0f), 5.0f);                   // clip to [0, EW_MAX]

    float4 v = *(const float4*)(g_xp + (size_t)src * 128 + lane * 4);
    float* o = out + (size_t)dst * 128 + lane * 4;
    asm volatile("red.global.add.v4.f32 [%0], {%1, %2, %3, %4};"
                 :: "l"(o), "f"(w * v.x), "f"(w * v.y), "f"(w * v.z), "f"(w * v.w)
                 : "memory");
    if (lane == 0) atomicAdd(&g_deg[dst], fabsf(w));
}

// ---------------------------------------------------------------------------
// K4: finalize: gelu(out/(deg+eps) + x_proj), float4-vectorized
// ---------------------------------------------------------------------------
__global__ void finalize_kernel(float4* __restrict__ out4, int n) {
    int i = blockIdx.x * blockDim.x + threadIdx.x;
    int total4 = n * 32;
    if (i >= total4) return;
    int nid = i >> 5;
    float inv = 1.0f / (g_deg[nid] + 1e-6f);
    float4 a = out4[i];
    float4 p = ((const float4*)g_xp)[i];
    float v0 = a.x * inv + p.x;
    float v1 = a.y * inv + p.y;
    float v2 = a.z * inv + p.z;
    float v3 = a.w * inv + p.w;
    const float is2 = 0.70710678118654752f;
    float4 r;
    r.x = 0.5f * v0 * (1.0f + erff(v0 * is2));
    r.y = 0.5f * v1 * (1.0f + erff(v1 * is2));
    r.z = 0.5f * v2 * (1.0f + erff(v2 * is2));
    r.w = 0.5f * v3 * (1.0f + erff(v3 * is2));
    out4[i] = r;
}

// ---------------------------------------------------------------------------
extern "C" void kernel_launch(void* const* d_in, const int* in_sizes, int n_in,
                              void* d_out, int out_size) {
    const float* x     = (const float*)d_in[0];
    const float* state = (const float*)d_in[1];
    const int*   ei    = (const int*)d_in[2];
    const float* ew    = (const float*)d_in[3];
    const float* Win   = (const float*)d_in[4];
    const float* bin   = (const float*)d_in[5];
    const float* W1    = (const float*)d_in[6];
    const float* b1    = (const float*)d_in[7];
    const float* W2    = (const float*)d_in[8];
    const float* b2    = (const float*)d_in[9];

    int n = in_sizes[0] / 128;     // 50000
    int E = in_sizes[3];           // 800000
    float* out = (float*)d_out;

    const int smem_proj = MTILE * P_A * 4 + 2 * 128 * P_B * 2;   // 79872 B
    static bool attr_set = false;
    if (!attr_set) {
        cudaFuncSetAttribute(proj_mma_kernel,
                             cudaFuncAttributeMaxDynamicSharedMemorySize, smem_proj);
        attr_set = true;
    }

    zero_kernel<<<2048, 256>>>((float4*)out, out_size / 4, n);
    prepW_kernel<<<(DIN * DOUT + 255) / 256, 256>>>(Win);
    proj_mma_kernel<<<(n + MTILE - 1) / MTILE, 128, smem_proj>>>(x, state, bin, n);
    gate_kernel<<<(n + 255) / 256, 256>>>(W1, b1, W2, b2, n);

    int edge_blocks = (int)(((long long)E * 32 + 255) / 256);
    edge_kernel<<<edge_blocks, 256>>>(ei, ew, out, E, n);

    finalize_kernel<<<(n * 32 + 255) / 256, 256>>>((float4*)out, n);
}